// round 1
// baseline (speedup 1.0000x reference)
#include <cuda_runtime.h>
#include <math.h>

#define BATCH 2
#define NSEQ  4096
#define CDIM  64
#define MTILE 64
#define KBLK  64

// Flash-attention style fused kernel:
//   S = Q K^T (over C=64), online softmax over key axis, O += P V, V == K == Q == x
//   out = gamma * O / l + x
//
// SMEM (exactly 48KB):
//   Qcm  [C][M]   channel-major Q tile (float4 fragment reads along rows)
//   Krm  [KB][C]  row-major K block (float4 fragment reads along channels, GEMM2)
//   Kbuf [C][KB]  channel-major K block for GEMM1; ALIASED as Ps[M][KB] after GEMM1
__global__ __launch_bounds__(256, 1)
void attn_flash_kernel(const float* __restrict__ x,
                       const float* __restrict__ gamma,
                       float* __restrict__ out)
{
    __shared__ float Qcm[CDIM * MTILE];
    __shared__ float Krm[KBLK * CDIM];
    __shared__ float Kbuf[CDIM * KBLK];   // union: Kcm[ch][key]  /  Ps[row][key]

    const int tid = threadIdx.x;
    const int tx  = tid & 15;     // 0..15 -> key/channel column group
    const int ty  = tid >> 4;     // 0..15 -> query row group
    const int r0  = ty * 4;
    const int c0  = tx * 4;

    const int qb = blockIdx.x * MTILE;
    const int b  = blockIdx.y;
    const float* xb = x + (size_t)b * NSEQ * CDIM;

    // ---- Load Q tile channel-major (transpose store: lane == row -> conflict-free) ----
    {
        const int r   = tid & 63;
        const int cg0 = tid >> 6;   // 0..3
        #pragma unroll
        for (int g = 0; g < 4; ++g) {
            const int cg = cg0 * 4 + g;      // 0..15
            float4 v = *(const float4*)&xb[(qb + r) * CDIM + cg * 4];
            Qcm[(cg * 4 + 0) * MTILE + r] = v.x;
            Qcm[(cg * 4 + 1) * MTILE + r] = v.y;
            Qcm[(cg * 4 + 2) * MTILE + r] = v.z;
            Qcm[(cg * 4 + 3) * MTILE + r] = v.w;
        }
    }

    float m[4], l[4], O[4][4];
    #pragma unroll
    for (int i = 0; i < 4; ++i) {
        m[i] = -1e30f; l[i] = 0.f;
        #pragma unroll
        for (int j = 0; j < 4; ++j) O[i][j] = 0.f;
    }

    for (int kb = 0; kb < NSEQ; kb += KBLK) {
        __syncthreads();  // prev GEMM2 done with Krm / Ps(Kbuf); Qcm visible on iter 0

        // ---- Load K block: row-major (coalesced) + channel-major (lane==row store) ----
        {
            const int c4 = tid & 15;
            #pragma unroll
            for (int g = 0; g < 4; ++g) {
                const int rr = (tid >> 4) + g * 16;   // 0..63
                float4 v = *(const float4*)&xb[(kb + rr) * CDIM + c4 * 4];
                *(float4*)&Krm[rr * CDIM + c4 * 4] = v;
            }
            const int r   = tid & 63;
            const int cg0 = tid >> 6;
            #pragma unroll
            for (int g = 0; g < 4; ++g) {
                const int cg = cg0 * 4 + g;
                float4 v = *(const float4*)&xb[(kb + r) * CDIM + cg * 4];
                Kbuf[(cg * 4 + 0) * KBLK + r] = v.x;
                Kbuf[(cg * 4 + 1) * KBLK + r] = v.y;
                Kbuf[(cg * 4 + 2) * KBLK + r] = v.z;
                Kbuf[(cg * 4 + 3) * KBLK + r] = v.w;
            }
        }
        __syncthreads();

        // ---- GEMM1: S[64x64] = Q Kblk^T, 4x4 per thread ----
        float S[4][4];
        #pragma unroll
        for (int i = 0; i < 4; ++i)
            #pragma unroll
            for (int j = 0; j < 4; ++j) S[i][j] = 0.f;

        #pragma unroll 16
        for (int ch = 0; ch < CDIM; ++ch) {
            float4 qf = *(const float4*)&Qcm[ch * MTILE + r0];
            float4 kf = *(const float4*)&Kbuf[ch * KBLK + c0];
            const float q[4] = {qf.x, qf.y, qf.z, qf.w};
            const float k[4] = {kf.x, kf.y, kf.z, kf.w};
            #pragma unroll
            for (int i = 0; i < 4; ++i)
                #pragma unroll
                for (int j = 0; j < 4; ++j)
                    S[i][j] = fmaf(q[i], k[j], S[i][j]);
        }
        __syncthreads();  // everyone done reading Kbuf(Kcm) -> safe to overwrite with P

        // ---- Online softmax (rows owned across 16 lanes sharing ty) ----
        float P[4][4];
        #pragma unroll
        for (int i = 0; i < 4; ++i) {
            float mb = fmaxf(fmaxf(S[i][0], S[i][1]), fmaxf(S[i][2], S[i][3]));
            #pragma unroll
            for (int s = 1; s < 16; s <<= 1)
                mb = fmaxf(mb, __shfl_xor_sync(0xffffffffu, mb, s));
            const float mn   = fmaxf(m[i], mb);
            const float corr = __expf(m[i] - mn);
            m[i] = mn;
            float ls = 0.f;
            #pragma unroll
            for (int j = 0; j < 4; ++j) { P[i][j] = __expf(S[i][j] - mn); ls += P[i][j]; }
            #pragma unroll
            for (int s = 1; s < 16; s <<= 1)
                ls += __shfl_xor_sync(0xffffffffu, ls, s);
            l[i] = l[i] * corr + ls;
            #pragma unroll
            for (int j = 0; j < 4; ++j) O[i][j] *= corr;
        }
        // store P tile (row-major over Kbuf)
        #pragma unroll
        for (int i = 0; i < 4; ++i)
            *(float4*)&Kbuf[(r0 + i) * KBLK + c0] =
                make_float4(P[i][0], P[i][1], P[i][2], P[i][3]);
        __syncthreads();

        // ---- GEMM2: O[64x64(chan)] += P Kblk ----
        #pragma unroll 16
        for (int k = 0; k < KBLK; ++k) {
            float4 vf = *(const float4*)&Krm[k * CDIM + c0];
            const float v[4] = {vf.x, vf.y, vf.z, vf.w};
            float p[4];
            #pragma unroll
            for (int i = 0; i < 4; ++i) p[i] = Kbuf[(r0 + i) * KBLK + k];  // broadcast
            #pragma unroll
            for (int i = 0; i < 4; ++i)
                #pragma unroll
                for (int j = 0; j < 4; ++j)
                    O[i][j] = fmaf(p[i], v[j], O[i][j]);
        }
    }

    // ---- Epilogue: out = gamma * O/l + x ----
    const float g = gamma[0];
    float* ob = out + (size_t)b * NSEQ * CDIM;
    #pragma unroll
    for (int i = 0; i < 4; ++i) {
        const float inv = 1.0f / l[i];
        const int row = qb + r0 + i;
        float4 xv = *(const float4*)&xb[row * CDIM + c0];
        float4 o;
        o.x = g * O[i][0] * inv + xv.x;
        o.y = g * O[i][1] * inv + xv.y;
        o.z = g * O[i][2] * inv + xv.z;
        o.w = g * O[i][3] * inv + xv.w;
        *(float4*)&ob[row * CDIM + c0] = o;
    }
}

extern "C" void kernel_launch(void* const* d_in, const int* in_sizes, int n_in,
                              void* d_out, int out_size)
{
    const float* x     = (const float*)d_in[0];
    const float* gamma = (const float*)d_in[1];
    float* out = (float*)d_out;
    (void)in_sizes; (void)n_in; (void)out_size;

    dim3 grid(NSEQ / MTILE, BATCH);
    attn_flash_kernel<<<grid, 256>>>(x, gamma, out);
}